// round 17
// baseline (speedup 1.0000x reference)
#include <cuda_runtime.h>
#include <cuda_fp16.h>
#include <cstdint>

#define N_NODES 50000
#define N_EDGES 800000
#define D 128
#define BN_EPS 1e-3f

#define AB 272         // bytes per fp16 smem row (136 fp16, pitch)
#define WBUF 34816     // bytes per 128x136 fp16 buffer
#define SPITCH 544     // stage fp32 row pitch bytes (512 data + 32 pad)

// Scratch
__device__ float  g_hidden[N_NODES * D];
__device__ float  g_counts[N_NODES];
__device__ __half g_sums[N_NODES * D];   // fp16 segment-sum accumulator

// ---------------------------------------------------------------------------
// helpers
// ---------------------------------------------------------------------------
__device__ __forceinline__ uint32_t smem_u32(const void* p) {
    uint32_t a;
    asm("{ .reg .u64 t; cvta.to.shared.u64 t, %1; cvt.u32.u64 %0, t; }" : "=r"(a) : "l"(p));
    return a;
}

// fp16x2 vector reduction: 16B = 8 half adds, one L2 atomic op
__device__ __forceinline__ void red_h2_v4(__half* addr, uint32_t a, uint32_t b,
                                          uint32_t c, uint32_t d) {
    asm volatile("red.global.add.noftz.v4.f16x2 [%0], {%1, %2, %3, %4};"
                 :: "l"(addr), "r"(a), "r"(b), "r"(c), "r"(d) : "memory");
}

__device__ __forceinline__ void prefetch_l1(const void* p) {
    asm volatile("prefetch.global.L1 [%0];" :: "l"(p));
}

__device__ __forceinline__ void ldsm_x4(uint32_t* r, uint32_t addr) {
    asm volatile("ldmatrix.sync.aligned.m8n8.x4.shared.b16 {%0,%1,%2,%3}, [%4];"
                 : "=r"(r[0]), "=r"(r[1]), "=r"(r[2]), "=r"(r[3]) : "r"(addr));
}

__device__ __forceinline__ void mma_f32acc(float* c, const uint32_t* a, const uint32_t* b) {
    asm volatile("mma.sync.aligned.m16n8k16.row.col.f32.f16.f16.f32 "
                 "{%0,%1,%2,%3}, {%4,%5,%6,%7}, {%8,%9}, {%0,%1,%2,%3};"
                 : "+f"(c[0]), "+f"(c[1]), "+f"(c[2]), "+f"(c[3])
                 : "r"(a[0]), "r"(a[1]), "r"(a[2]), "r"(a[3]), "r"(b[0]), "r"(b[1]));
}

__device__ __forceinline__ void mma_fp16acc(uint32_t* c, const uint32_t* a, const uint32_t* b) {
    asm volatile("mma.sync.aligned.m16n8k16.row.col.f16.f16.f16.f16 "
                 "{%0,%1}, {%2,%3,%4,%5}, {%6,%7}, {%0,%1};"
                 : "+r"(c[0]), "+r"(c[1])
                 : "r"(a[0]), "r"(a[1]), "r"(a[2]), "r"(a[3]), "r"(b[0]), "r"(b[1]));
}

__device__ __forceinline__ uint32_t pack_h2(__half lo, __half hi) {
    return (uint32_t)__half_as_ushort(lo) | ((uint32_t)__half_as_ushort(hi) << 16);
}

__device__ __forceinline__ float tanh_fast(float x) {
    float y; asm("tanh.approx.f32 %0, %1;" : "=f"(y) : "f"(x)); return y;
}
__device__ __forceinline__ float sigmoid_fast(float x) {
    return fmaf(tanh_fast(0.5f * x), 0.5f, 0.5f);
}

__device__ __forceinline__ void cp16(uint32_t saddr, const void* g) {
    asm volatile("cp.async.cg.shared.global [%0], [%1], 16;" :: "r"(saddr), "l"(g));
}
#define CP_COMMIT() asm volatile("cp.async.commit_group;" ::: "memory")
#define CP_WAIT0()  asm volatile("cp.async.wait_group 0;" ::: "memory")

// ---------------------------------------------------------------------------
// K1: node GEMM + fused zero of g_sums/counts (R16-passing, unchanged)
// ---------------------------------------------------------------------------
#define NG_SMEM 70656

__global__ __launch_bounds__(512, 1)
void node_gemm_kernel(const float* __restrict__ nf,
                      const float* __restrict__ W,
                      const float* __restrict__ b) {
    extern __shared__ __align__(16) char smem[];
    float* sB = reinterpret_cast<float*>(smem);
    char*  sA = smem + 1024;
    char*  sW = smem + 35840;

    const int t = threadIdx.x, w = t >> 5, lane = t & 31;
    const int wm = w & 3, wn = w >> 2;

    {   // zero g_sums (fp16) + counts
        int gid = blockIdx.x * 512 + t;
        int gstride = gridDim.x * 512;
        const int nu4 = N_NODES * D / 8;   // uint4 = 8 halves
        uint4 z = make_uint4(0u, 0u, 0u, 0u);
        for (int i = gid; i < nu4; i += gstride)
            reinterpret_cast<uint4*>(g_sums)[i] = z;
        for (int i = gid; i < N_NODES; i += gstride)
            g_counts[i] = 0.f;
    }

    if (t < 128) sB[t] = b[t];

    for (int idx = t; idx < 16384; idx += 512) {
        int k = idx >> 7, n = idx & 127;
        *reinterpret_cast<__half*>(sW + n * AB + k * 2) = __float2half_rn(W[idx]);
    }
    __syncthreads();

    const uint32_t sbA = smem_u32(sA);
    const uint32_t sbW = smem_u32(sW);

    const int ra = lane & 15;
    const int ka = (lane >> 4) * 16;
    const int rb = (lane & 7) + ((lane >> 4) & 1) * 8;
    const int kb = ((lane >> 3) & 1) * 16;
    const uint32_t aoff = sbA + (uint32_t)((wm * 32 + ra) * AB + ka);
    const uint32_t boff = sbW + (uint32_t)((wn * 32 + rb) * AB + kb);

    const int ntiles = (N_NODES + 127) / 128;  // 391
    for (int tile = blockIdx.x; tile < ntiles; tile += gridDim.x) {
        __syncthreads();
        const int r0 = tile * 128;
        #pragma unroll
        for (int i = 0; i < 8; i++) {
            int idx = t + i * 512;
            int row = idx >> 5, c16 = idx & 31;
            int grow = r0 + row;
            float4 v = make_float4(0.f, 0.f, 0.f, 0.f);
            if (grow < N_NODES)
                v = *reinterpret_cast<const float4*>(&nf[(size_t)grow * 128 + c16 * 4]);
            *reinterpret_cast<uint2*>(sA + row * AB + c16 * 8) = make_uint2(
                pack_h2(__float2half_rn(v.x), __float2half_rn(v.y)),
                pack_h2(__float2half_rn(v.z), __float2half_rn(v.w)));
        }
        __syncthreads();

        float acc[2][4][4];
        #pragma unroll
        for (int mt = 0; mt < 2; mt++)
            #pragma unroll
            for (int nt = 0; nt < 4; nt++)
                #pragma unroll
                for (int i = 0; i < 4; i++) acc[mt][nt][i] = 0.f;

        #pragma unroll
        for (int ks = 0; ks < 8; ks++) {
            uint32_t ah[2][4];
            ldsm_x4(ah[0], aoff + ks * 32);
            ldsm_x4(ah[1], aoff + 16 * AB + ks * 32);
            uint32_t bh[8];
            ldsm_x4(&bh[0], boff + ks * 32);
            ldsm_x4(&bh[4], boff + (uint32_t)(16 * AB) + ks * 32);
            #pragma unroll
            for (int mt = 0; mt < 2; mt++)
                #pragma unroll
                for (int nt = 0; nt < 4; nt++)
                    mma_f32acc(acc[mt][nt], ah[mt], &bh[nt * 2]);
        }

        #pragma unroll
        for (int mt = 0; mt < 2; mt++) {
            #pragma unroll
            for (int rr = 0; rr < 2; rr++) {
                int grow = r0 + wm * 32 + mt * 16 + (lane >> 2) + rr * 8;
                if (grow < N_NODES) {
                    float* hp = &g_hidden[(size_t)grow * 128];
                    #pragma unroll
                    for (int nt = 0; nt < 4; nt++) {
                        int c = wn * 32 + nt * 8 + (lane & 3) * 2;
                        float2 o;
                        o.x = acc[mt][nt][rr * 2 + 0] + sB[c];
                        o.y = acc[mt][nt][rr * 2 + 1] + sB[c + 1];
                        *reinterpret_cast<float2*>(hp + c) = o;
                    }
                }
            }
        }
    }
}

// ---------------------------------------------------------------------------
// K2: edge kernel — R16-passing structure + L1 prefetch of gather lines
//     under the mma window.
// ---------------------------------------------------------------------------
#define EK_SMEM 210944
#define OFF_A   2048
#define OFF_W   71680
#define OFF_S   141312

__global__ __launch_bounds__(1024, 1)
void edge_kernel(const float* __restrict__ ef,
                 const float* __restrict__ Wg, const float* __restrict__ bgp,
                 const float* __restrict__ Wf, const float* __restrict__ bfp,
                 const int*   __restrict__ eidx) {
    extern __shared__ __align__(16) char smem[];
    float* sBg  = reinterpret_cast<float*>(smem + 1024);
    float* sBf  = reinterpret_cast<float*>(smem + 1536);
    char*  sA   = smem + OFF_A;
    char*  sW   = smem + OFF_W;
    char*  sS   = smem + OFF_S;

    const int t = threadIdx.x, w = t >> 5, lane = t & 31;
    const int wm = w & 3, wn = w >> 2;      // wm 0..3, wn 0..7
    const int q  = lane & 3;                // quad role

    const uint32_t sbA = smem_u32(sA);
    const uint32_t sbW = smem_u32(sW);
    const uint32_t sbS = smem_u32(sS);

    const int ntiles = N_EDGES / 128;
    const int tile0 = blockIdx.x;

    // prefetch tile0 raw fp32 into stage (4 x 16B per thread)
    {
        const int e0 = tile0 * 128;
        #pragma unroll
        for (int i = 0; i < 4; i++) {
            int idx = t + i * 1024;
            int row = idx >> 5, c16 = idx & 31;
            cp16(sbS + (uint32_t)(row * SPITCH + c16 * 16),
                 &ef[(size_t)(e0 + row) * 128 + c16 * 4]);
        }
        CP_COMMIT();
    }

    if (t < 128) { sBg[t] = bgp[t]; sBf[t] = bfp[t]; }

    for (int m = 0; m < 2; m++) {
        const float* W = m ? Wf : Wg;
        char* buf = sW + m * WBUF;
        for (int idx = t; idx < 16384; idx += 1024) {
            int k = idx >> 7, n = idx & 127;
            *reinterpret_cast<__half*>(buf + n * AB + k * 2) = __float2half_rn(W[idx]);
        }
    }
    CP_WAIT0();
    __syncthreads();

    // convert tile0 into A buffer 0
    #pragma unroll
    for (int i = 0; i < 4; i++) {
        int idx = t + i * 1024;
        int row = idx >> 5, c16 = idx & 31;
        float4 v = *reinterpret_cast<const float4*>(sS + row * SPITCH + c16 * 16);
        *reinterpret_cast<uint2*>(sA + row * AB + c16 * 8) = make_uint2(
            pack_h2(__float2half_rn(v.x), __float2half_rn(v.y)),
            pack_h2(__float2half_rn(v.z), __float2half_rn(v.w)));
    }
    __syncthreads();

    // prefetch tile0+grid
    {
        int tn = tile0 + gridDim.x;
        if (tn >= ntiles) tn = tile0;
        const int en = tn * 128;
        #pragma unroll
        for (int i = 0; i < 4; i++) {
            int idx = t + i * 1024;
            int row = idx >> 5, c16 = idx & 31;
            cp16(sbS + (uint32_t)(row * SPITCH + c16 * 16),
                 &ef[(size_t)(en + row) * 128 + c16 * 4]);
        }
        CP_COMMIT();
    }

    const int ra = lane & 15;
    const int ka = (lane >> 4) * 16;
    const int rb = (lane & 7) + ((lane >> 4) & 1) * 8;
    const int kb = ((lane >> 3) & 1) * 16;

    const uint32_t aoff0 = sbA + (uint32_t)((wm * 32 + ra) * AB + ka);
    const uint32_t boff  = sbW + (uint32_t)((wn * 16 + rb) * AB + kb);

    int cur = 0;
    for (int tile = tile0; tile < ntiles; tile += gridDim.x) {
        const int e0 = tile * 128;

        // indices for BOTH fragment rows (r, r+8) per mt
        int srcR[2][2], dstR[2][2];
        #pragma unroll
        for (int mt = 0; mt < 2; mt++) {
            int r = wm * 32 + mt * 16 + (lane >> 2);
            int2 p0 = *reinterpret_cast<const int2*>(&eidx[(size_t)(e0 + r) * 2]);
            int2 p1 = *reinterpret_cast<const int2*>(&eidx[(size_t)(e0 + r + 8) * 2]);
            srcR[mt][0] = p0.x; dstR[mt][0] = p0.y;
            srcR[mt][1] = p1.x; dstR[mt][1] = p1.y;
        }
        // L1-prefetch the 4 gather lines this thread will read in the epilogue;
        // the ~240-580cyc L2/DRAM latency hides under the mma below.
        #pragma unroll
        for (int mt = 0; mt < 2; mt++) {
            prefetch_l1(&g_hidden[(size_t)dstR[mt][0] * 128 + wn * 16]);
            prefetch_l1(&g_hidden[(size_t)dstR[mt][1] * 128 + wn * 16]);
        }
        if (t < 128)
            atomicAdd(&g_counts[eidx[(size_t)(e0 + t) * 2]], 1.0f);

        const uint32_t aoff = aoff0 + (uint32_t)(cur * WBUF);
        uint32_t acc[2][2][2][2];   // [matrix][mt][nt][reg]
        #pragma unroll
        for (int m = 0; m < 2; m++)
            #pragma unroll
            for (int mt = 0; mt < 2; mt++)
                #pragma unroll
                for (int nt = 0; nt < 2; nt++) {
                    acc[m][mt][nt][0] = 0u; acc[m][mt][nt][1] = 0u;
                }

        #pragma unroll
        for (int ks = 0; ks < 8; ks++) {
            uint32_t ah[2][4];
            ldsm_x4(ah[0], aoff + ks * 32);
            ldsm_x4(ah[1], aoff + 16 * AB + ks * 32);
            #pragma unroll
            for (int m = 0; m < 2; m++) {
                uint32_t bh[4];
                ldsm_x4(bh, boff + (uint32_t)(m * WBUF) + ks * 32);
                #pragma unroll
                for (int mt = 0; mt < 2; mt++)
                    #pragma unroll
                    for (int nt = 0; nt < 2; nt++)
                        mma_fp16acc(acc[m][mt][nt], ah[mt], &bh[nt * 2]);
            }
        }

        CP_WAIT0();
        __syncthreads();

        // convert stage -> A[nxt]
        {
            char* An = sA + (cur ^ 1) * WBUF;
            #pragma unroll
            for (int i = 0; i < 4; i++) {
                int idx = t + i * 1024;
                int row = idx >> 5, c16 = idx & 31;
                float4 v = *reinterpret_cast<const float4*>(sS + row * SPITCH + c16 * 16);
                *reinterpret_cast<uint2*>(An + row * AB + c16 * 8) = make_uint2(
                    pack_h2(__float2half_rn(v.x), __float2half_rn(v.y)),
                    pack_h2(__float2half_rn(v.z), __float2half_rn(v.w)));
            }
        }
        __syncthreads();

        // prefetch tile+2*grid
        {
            int tn = tile + 2 * gridDim.x;
            if (tn >= ntiles) tn = tile;
            const int en = tn * 128;
            #pragma unroll
            for (int i = 0; i < 4; i++) {
                int idx = t + i * 1024;
                int row = idx >> 5, c16 = idx & 31;
                cp16(sbS + (uint32_t)(row * SPITCH + c16 * 16),
                     &ef[(size_t)(en + row) * 128 + c16 * 4]);
            }
            CP_COMMIT();
        }

        // Epilogue: messages on native fragment cols, quad-shuffle to 8-col
        // groups, lanes q0/q1 issue red.v4.f16x2 into fp16 g_sums.
        #pragma unroll
        for (int mt = 0; mt < 2; mt++) {
            #pragma unroll
            for (int nt = 0; nt < 2; nt++) {
                const int C = wn * 16 + nt * 8;
                const int c = C + q * 2;
                float2 nbr = *reinterpret_cast<const float2*>(
                    &g_hidden[(size_t)dstR[mt][0] * 128 + c]);
                float2 nbs = *reinterpret_cast<const float2*>(
                    &g_hidden[(size_t)dstR[mt][1] * 128 + c]);
                uint32_t a0 = acc[0][mt][nt][0], a1 = acc[0][mt][nt][1];
                uint32_t f0 = acc[1][mt][nt][0], f1 = acc[1][mt][nt][1];
                float2 gr = __half22float2(*reinterpret_cast<__half2*>(&a0));
                float2 gs = __half22float2(*reinterpret_cast<__half2*>(&a1));
                float2 fr = __half22float2(*reinterpret_cast<__half2*>(&f0));
                float2 fs = __half22float2(*reinterpret_cast<__half2*>(&f1));
                float bg0 = sBg[c], bg1 = sBg[c + 1];
                float bf0 = sBf[c], bf1 = sBf[c + 1];

                float m0 = sigmoid_fast(gr.x + bg0) * (fr.x + bf0) * nbr.x;
                float m1 = sigmoid_fast(gr.y + bg1) * (fr.y + bf1) * nbr.y;
                float s0 = sigmoid_fast(gs.x + bg0) * (fs.x + bf0) * nbs.x;
                float s1 = sigmoid_fast(gs.y + bg1) * (fs.y + bf1) * nbs.y;

                uint32_t M0 = pack_h2(__float2half_rn(m0), __float2half_rn(m1));
                uint32_t M1 = pack_h2(__float2half_rn(s0), __float2half_rn(s1));

                uint32_t v0[4], v1[4];
                #pragma unroll
                for (int j = 0; j < 4; j++) {
                    v0[j] = __shfl_sync(0xffffffffu, M0, j, 4);
                    v1[j] = __shfl_sync(0xffffffffu, M1, j, 4);
                }
                if (q == 0)
                    red_h2_v4(&g_sums[(size_t)srcR[mt][0] * 128 + C],
                              v0[0], v0[1], v0[2], v0[3]);
                else if (q == 1)
                    red_h2_v4(&g_sums[(size_t)srcR[mt][1] * 128 + C],
                              v1[0], v1[1], v1[2], v1[3]);
            }
        }

        cur ^= 1;
    }
}

// ---------------------------------------------------------------------------
// K3: finalize — out = relu(bn(hidden + sums/max(counts,1))), sums from fp16
// ---------------------------------------------------------------------------
__global__ void finalize_kernel(const float* __restrict__ gamma,
                                const float* __restrict__ beta,
                                const float* __restrict__ mean,
                                const float* __restrict__ var,
                                float* __restrict__ out) {
    int idx = blockIdx.x * blockDim.x + threadIdx.x;
    const int total = N_NODES * 32;
    if (idx >= total) return;
    int node = idx >> 5;
    int qq   = idx & 31;
    float inv = 1.f / fmaxf(g_counts[node], 1.f);

    uint2 sv = reinterpret_cast<const uint2*>(g_sums)[idx];
    float2 s01 = __half22float2(*reinterpret_cast<__half2*>(&sv.x));
    float2 s23 = __half22float2(*reinterpret_cast<__half2*>(&sv.y));

    float4 h  = *reinterpret_cast<const float4*>(&g_hidden[node * D + qq * 4]);
    float4 mu = *reinterpret_cast<const float4*>(&mean[qq * 4]);
    float4 vr = *reinterpret_cast<const float4*>(&var[qq * 4]);
    float4 ga = *reinterpret_cast<const float4*>(&gamma[qq * 4]);
    float4 be = *reinterpret_cast<const float4*>(&beta[qq * 4]);

    float4 o;
    o.x = fmaxf((h.x + s01.x * inv - mu.x) * rsqrtf(vr.x + BN_EPS) * ga.x + be.x, 0.f);
    o.y = fmaxf((h.y + s01.y * inv - mu.y) * rsqrtf(vr.y + BN_EPS) * ga.y + be.y, 0.f);
    o.z = fmaxf((h.z + s23.x * inv - mu.z) * rsqrtf(vr.z + BN_EPS) * ga.z + be.z, 0.f);
    o.w = fmaxf((h.w + s23.y * inv - mu.w) * rsqrtf(vr.w + BN_EPS) * ga.w + be.w, 0.f);
    reinterpret_cast<float4*>(out)[idx] = o;
}

// ---------------------------------------------------------------------------
// launch
// ---------------------------------------------------------------------------
extern "C" void kernel_launch(void* const* d_in, const int* in_sizes, int n_in,
                              void* d_out, int out_size) {
    const float* nf    = (const float*)d_in[0];
    const float* ef    = (const float*)d_in[1];
    const float* Wn    = (const float*)d_in[2];
    const float* bn_   = (const float*)d_in[3];
    const float* Wg    = (const float*)d_in[4];
    const float* bg    = (const float*)d_in[5];
    const float* Wf    = (const float*)d_in[6];
    const float* bf    = (const float*)d_in[7];
    const float* gamma = (const float*)d_in[8];
    const float* beta  = (const float*)d_in[9];
    const float* mean  = (const float*)d_in[10];
    const float* var   = (const float*)d_in[11];
    const int*   eidx  = (const int*)d_in[12];
    float* out = (float*)d_out;

    int dev = 0, nsm = 148;
    cudaGetDevice(&dev);
    cudaDeviceGetAttribute(&nsm, cudaDevAttrMultiProcessorCount, dev);
    cudaFuncSetAttribute(node_gemm_kernel, cudaFuncAttributeMaxDynamicSharedMemorySize, NG_SMEM);
    cudaFuncSetAttribute(edge_kernel,      cudaFuncAttributeMaxDynamicSharedMemorySize, EK_SMEM);

    node_gemm_kernel<<<nsm, 512, NG_SMEM>>>(nf, Wn, bn_);
    edge_kernel<<<nsm, 1024, EK_SMEM>>>(ef, Wg, bg, Wf, bf, eidx);
    finalize_kernel<<<(N_NODES * 32 + 255) / 256, 256>>>(gamma, beta, mean, var, out);
}